// round 14
// baseline (speedup 1.0000x reference)
#include <cuda_runtime.h>
#include <cuda_fp16.h>
#include <cstdint>

// ---------------------------------------------------------------------------
// EdgeDense: z = x @ W + b  (N x 32, stored fp16), then
//            out[e] = w_e * (z[rows[e]] + z[cols[e]])   (fp32 out)
// N_NODES = 100000, IN = 128, OUT = 32, E = 1.6M
// GEMM via fp16 mma.sync m16n8k16 (f32 accum) + cp.async pipeline;
// edge kernel gather/scatter (config frozen since R11).
// ---------------------------------------------------------------------------

#define MAX_NODES 100000
#define IN_F 128
#define OUT_F 32

#define GB 256                  // gemm threads per block (8 warps)
#define NPB 128                 // nodes per block -> 782 blocks
#define NCH 8                   // k-chunks of 16
#define SXS 24                  // x staging stride (floats): 96B rows,
                                // conflict-free LDS.64 (8g+2t per phase)
#define ZTS 40                  // epilogue z tile stride (halves)

// z in fp16: 100000 * 32 * 2B = 6.4 MB (L2-resident). Device global.
__device__ __half2 g_zh[(size_t)MAX_NODES * (OUT_F / 2)];
// Index-dtype flag: 1 => indices are int64, 0 => indices are int32.
__device__ int g_idx64;

// Pack two fp32 into fp16x2 (lo first).
#define CVT_F16X2(d, hi, lo) \
    asm("cvt.rn.f16x2.f32 %0, %1, %2;" : "=r"(d) : "f"(hi), "f"(lo))

// 16B async copy global->shared; src_sz=0 => zero-fill (no src read).
#define CP_ASYNC16(dst_s, src_g, src_sz) \
    asm volatile("cp.async.ca.shared.global [%0], [%1], 16, %2;" \
                 :: "r"(dst_s), "l"(src_g), "r"(src_sz))
#define CP_COMMIT() asm volatile("cp.async.commit_group;")
#define CP_WAIT0()  asm volatile("cp.async.wait_group 0;" ::: "memory")

// D(16x8,f32) += A(16x16,f16,row) * B(16x8,f16,col)
#define MMA_F16(d, a, b0, b1) \
    asm("mma.sync.aligned.m16n8k16.row.col.f32.f16.f16.f32 " \
        "{%0,%1,%2,%3}, {%4,%5,%6,%7}, {%8,%9}, {%0,%1,%2,%3};" \
        : "+f"((d)[0]), "+f"((d)[1]), "+f"((d)[2]), "+f"((d)[3]) \
        : "r"((a)[0]), "r"((a)[1]), "r"((a)[2]), "r"((a)[3]), \
          "r"(b0), "r"(b1))

// ---------------------------------------------------------------------------
// GEMM: z^T = W^T(32x128) @ x^T(128xN), m16n8k16 fp16 MMA, f32 accumulate.
// fp16 inputs have the SAME 11-bit mantissa as tf32 -> precision unchanged;
// k16 halves the MMA count (200k) and the operand LDS stream vs tf32 k8
// (the legacy-mma issue path was the measured binder at ~18us).
//   A = W^T fragments prebuilt PACKED fp16 in smem (8 KB; per-lane order,
//       1 LDS.128 per (mt, chunk)).
//   B = x staged per 16-k chunk via cp.async double-buffer (stride 24
//       floats = 96B rows; 8g+2t banks distinct per 16-lane phase ->
//       conflict-free LDS.64); fp32 pairs cvt.rn.f16x2 at the operand load.
// m16n8k16 fragment maps (g=lane>>2, t=lane&3):
//   a0={A[g][2t],A[g][2t+1]}       a1={A[g+8][2t],A[g+8][2t+1]}
//   a2={A[g][2t+8],A[g][2t+9]}     a3={A[g+8][2t+8],A[g+8][2t+9]}
//   b0={B[2t][g],B[2t+1][g]}       b1={B[2t+8][g],B[2t+9][g]}
//   d0=D[g][2t] d1=D[g][2t+1] d2=D[g+8][2t] d3=D[g+8][2t+1]
// smem 32KB -> 7 CTAs/SM -> 1036 slots >= 782 blocks: single wave.
// Epilogue: bias, fp16, staged via smem (buffer 0 reused) for coalesced
// 16B stores. Block 0 runs the edge-index dtype probe (JAX x64-off hazard:
// int32 read as int64 words is >= 2^32 whenever the odd word != 0).
// ---------------------------------------------------------------------------
__global__ __launch_bounds__(GB)
void gemm_kernel(const float4* __restrict__ x4,
                 const float*  __restrict__ W,    // [128][32] row-major
                 const float*  __restrict__ b,    // [32]
                 __half2* __restrict__ zh,
                 int n_nodes,
                 const long long* __restrict__ idx_probe) {
    __shared__ unsigned sWf[2 * NCH * 32 * 4];    // 8 KB A fragments (fp16x2)
    __shared__ float sx[2][NPB * SXS];            // 2 x 12 KB x buffers
    __shared__ int s_bad;

    int tid = threadIdx.x;
    int lane = tid & 31, wp = tid >> 5;           // wp 0..7
    int g = lane >> 2, t = lane & 3;
    int base = blockIdx.x * NPB;

    // Build packed-fp16 A fragments: sWf[((mt*NCH+kt)*32+lane)*4 + r]
    // A[o][k] = W[k*32+o].
    for (int idx = tid; idx < 2 * NCH * 32; idx += GB) {
        int mt = idx >> 8;                   // 0..1
        int kt = (idx >> 5) & 7;             // 0..7
        int ln = idx & 31;
        int gg = ln >> 2, tt = ln & 3;
        int k0 = kt * 16 + 2 * tt, ob = mt * 16 + gg;
        unsigned r0, r1, r2, r3;
        CVT_F16X2(r0, W[(k0 + 1) * OUT_F + ob],     W[k0 * OUT_F + ob]);
        CVT_F16X2(r1, W[(k0 + 1) * OUT_F + ob + 8], W[k0 * OUT_F + ob + 8]);
        CVT_F16X2(r2, W[(k0 + 9) * OUT_F + ob],     W[(k0 + 8) * OUT_F + ob]);
        CVT_F16X2(r3, W[(k0 + 9) * OUT_F + ob + 8], W[(k0 + 8) * OUT_F + ob + 8]);
        *reinterpret_cast<uint4*>(&sWf[idx * 4]) = make_uint4(r0, r1, r2, r3);
    }
    if (blockIdx.x == 0 && tid == 0) s_bad = 0;

    if (blockIdx.x == 0) {
        long long v = idx_probe[tid];
        if (v < 0 || v >= (long long)n_nodes) atomicOr(&s_bad, 1);
    }

    // Staging geometry: 2 x 16B cp.async per thread per chunk
    // (128 nodes x 64B per 16-k chunk = 512 float4).
    int sn[2], sq[2];
    unsigned ssz[2];
    const float4* gsrc[2];
    #pragma unroll
    for (int j = 0; j < 2; j++) {
        int i = j * GB + tid;
        sn[j] = i >> 2;                 // node 0..127
        sq[j] = i & 3;                  // float4 slot within 16-k chunk
        int gn = base + sn[j];
        ssz[j] = (gn < n_nodes) ? 16u : 0u;
        gsrc[j] = &x4[(size_t)(gn < n_nodes ? gn : 0) * (IN_F / 4) + sq[j]];
    }
    unsigned sdst[2][2];
    #pragma unroll
    for (int bu = 0; bu < 2; bu++)
        #pragma unroll
        for (int j = 0; j < 2; j++)
            sdst[bu][j] = (unsigned)__cvta_generic_to_shared(
                &sx[bu][sn[j] * SXS + sq[j] * 4]);

    // Issue chunk 0 into buffer 0.
    #pragma unroll
    for (int j = 0; j < 2; j++) CP_ASYNC16(sdst[0][j], gsrc[j], ssz[j]);
    CP_COMMIT();

    float d[2][2][4];
    #pragma unroll
    for (int mt = 0; mt < 2; mt++)
        #pragma unroll
        for (int nt = 0; nt < 2; nt++)
            #pragma unroll
            for (int r = 0; r < 4; r++) d[mt][nt][r] = 0.f;

    #pragma unroll
    for (int c = 0; c < NCH; c++) {
        CP_WAIT0();
        __syncthreads();   // chunk c visible; all warps past compute c-1

        if (c < NCH - 1) {
            #pragma unroll
            for (int j = 0; j < 2; j++)
                CP_ASYNC16(sdst[(c + 1) & 1][j],
                           gsrc[j] + (c + 1) * 4, ssz[j]);
            CP_COMMIT();
        }

        const float* xb = sx[c & 1];

        // A fragments for this chunk (one LDS.128 per mt, conflict-free).
        unsigned a[2][4];
        #pragma unroll
        for (int mt = 0; mt < 2; mt++)
            *reinterpret_cast<uint4*>(a[mt]) =
                *reinterpret_cast<const uint4*>(
                    &sWf[((mt * NCH + c) * 32 + lane) * 4]);

        #pragma unroll
        for (int nt = 0; nt < 2; nt++) {
            int nl = wp * 16 + nt * 8 + g;
            float2 v0 = *reinterpret_cast<const float2*>(
                &xb[nl * SXS + 2 * t]);
            float2 v1 = *reinterpret_cast<const float2*>(
                &xb[nl * SXS + 8 + 2 * t]);
            unsigned b0, b1;
            CVT_F16X2(b0, v0.y, v0.x);
            CVT_F16X2(b1, v1.y, v1.x);
            MMA_F16(d[0][nt], a[0], b0, b1);
            MMA_F16(d[1][nt], a[1], b0, b1);
        }
    }
    __syncthreads();   // all MMAs done before buffer 0 is reused as zt

    // Epilogue: bias + fp16, stage via smem (sx[0] reused, half zt[128][40]).
    float bias_v[4];
    bias_v[0] = __ldg(&b[g]);
    bias_v[1] = __ldg(&b[g + 8]);
    bias_v[2] = __ldg(&b[16 + g]);
    bias_v[3] = __ldg(&b[16 + g + 8]);

    __half* zt = reinterpret_cast<__half*>(sx[0]);
    #pragma unroll
    for (int mt = 0; mt < 2; mt++) {
        #pragma unroll
        for (int nt = 0; nt < 2; nt++) {
            int n0 = wp * 16 + nt * 8 + 2 * t;
            int o0 = mt * 16 + g;
            zt[n0 * ZTS + o0]           = __float2half(d[mt][nt][0] + bias_v[mt * 2]);
            zt[(n0 + 1) * ZTS + o0]     = __float2half(d[mt][nt][1] + bias_v[mt * 2]);
            zt[n0 * ZTS + o0 + 8]       = __float2half(d[mt][nt][2] + bias_v[mt * 2 + 1]);
            zt[(n0 + 1) * ZTS + o0 + 8] = __float2half(d[mt][nt][3] + bias_v[mt * 2 + 1]);
        }
    }
    __syncthreads();

    // Coalesced store: 128 nodes x 64B, 2 x 16B per thread.
    #pragma unroll
    for (int p = 0; p < 2; p++) {
        int i = p * GB + tid;           // 0..511
        int nl = i >> 2;
        int part = i & 3;
        int node = base + nl;
        if (node < n_nodes) {
            uint4 v = *reinterpret_cast<const uint4*>(&zt[nl * ZTS + part * 8]);
            *reinterpret_cast<uint4*>(
                reinterpret_cast<char*>(zh) + (size_t)node * 64 + part * 16) = v;
        }
    }

    if (blockIdx.x == 0) {
        __syncthreads();
        if (tid == 0) g_idx64 = s_bad ? 0 : 1;
    }
}

// ---------------------------------------------------------------------------
// Edge kernel: byte-identical to R11-R13 (measured 47.7-48.3us -- family
// optimum; all lane-width / occupancy / persistence perturbations
// regressed). 8 lanes per edge, uint2 __ldcg gathers (4 distinct z rows
// per gather instr; L1 fill skipped); 4 CONSECUTIVE edges per thread with
// vectorized index/val loads; front-batched gathers (MLP=8); stores
// 1 STG.128/lane/edge, streaming.
// ---------------------------------------------------------------------------
__global__ __launch_bounds__(256)
void edge_kernel(const __half2* __restrict__ zh,
                 const void* __restrict__ rows_raw,
                 const void* __restrict__ cols_raw,
                 const float* __restrict__ vals,
                 float4* __restrict__ out,
                 int n_edges) {
    int gid = blockIdx.x * blockDim.x + threadIdx.x;
    int m = gid >> 3;
    int c = gid & 7;
    int eb = m * 4;
    if (eb >= n_edges) return;

    const uint2* zb = reinterpret_cast<const uint2*>(zh);

    if (eb + 3 < n_edges) {
        int r[4], cc[4];
        float w[4];
        if (g_idx64) {
            const int4* rp = (const int4*)rows_raw;
            const int4* cp = (const int4*)cols_raw;
            int4 ra = __ldcs(&rp[2 * m]), rb = __ldcs(&rp[2 * m + 1]);
            int4 ca = __ldcs(&cp[2 * m]), cb = __ldcs(&cp[2 * m + 1]);
            r[0] = ra.x; r[1] = ra.z; r[2] = rb.x; r[3] = rb.z;
            cc[0] = ca.x; cc[1] = ca.z; cc[2] = cb.x; cc[3] = cb.z;
        } else {
            int4 ra = __ldcs(&((const int4*)rows_raw)[m]);
            int4 ca = __ldcs(&((const int4*)cols_raw)[m]);
            r[0] = ra.x; r[1] = ra.y; r[2] = ra.z; r[3] = ra.w;
            cc[0] = ca.x; cc[1] = ca.y; cc[2] = ca.z; cc[3] = ca.w;
        }
        float4 wv = __ldcs(&((const float4*)vals)[m]);
        w[0] = wv.x; w[1] = wv.y; w[2] = wv.z; w[3] = wv.w;

        uint2 ga[4], gd[4];
        #pragma unroll
        for (int q = 0; q < 4; q++) {
            ga[q] = __ldcg(&zb[(size_t)r[q] * 8 + c]);
            gd[q] = __ldcg(&zb[(size_t)cc[q] * 8 + c]);
        }

        #pragma unroll
        for (int q = 0; q < 4; q++) {
            float2 fa0 = __half22float2(*reinterpret_cast<__half2*>(&ga[q].x));
            float2 fd0 = __half22float2(*reinterpret_cast<__half2*>(&gd[q].x));
            float2 fa1 = __half22float2(*reinterpret_cast<__half2*>(&ga[q].y));
            float2 fd1 = __half22float2(*reinterpret_cast<__half2*>(&gd[q].y));
            float4 o;
            o.x = w[q] * (fa0.x + fd0.x);
            o.y = w[q] * (fa0.y + fd0.y);
            o.z = w[q] * (fa1.x + fd1.x);
            o.w = w[q] * (fa1.y + fd1.y);
            __stcs(&out[(size_t)(eb + q) * 8 + c], o);
        }
    } else {
        // Tail: per-edge guarded scalar path.
        int sh = g_idx64;
        const int* rp = (const int*)rows_raw;
        const int* cp = (const int*)cols_raw;
        for (int q = 0; q < 4; q++) {
            int e = eb + q;
            if (e >= n_edges) break;
            int rr = __ldcs(&rp[e << sh]);
            int cl = __ldcs(&cp[e << sh]);
            float ww = __ldcs(&vals[e]);
            uint2 a = __ldcg(&zb[(size_t)rr * 8 + c]);
            uint2 dd = __ldcg(&zb[(size_t)cl * 8 + c]);
            float2 fa0 = __half22float2(*reinterpret_cast<__half2*>(&a.x));
            float2 fd0 = __half22float2(*reinterpret_cast<__half2*>(&dd.x));
            float2 fa1 = __half22float2(*reinterpret_cast<__half2*>(&a.y));
            float2 fd1 = __half22float2(*reinterpret_cast<__half2*>(&dd.y));
            float4 o;
            o.x = ww * (fa0.x + fd0.x);
            o.y = ww * (fa0.y + fd0.y);
            o.z = ww * (fa1.x + fd1.x);
            o.w = ww * (fa1.y + fd1.y);
            __stcs(&out[(size_t)e * 8 + c], o);
        }
    }
}

// ---------------------------------------------------------------------------
// Launch. Inputs (metadata order): x, W, b, edge_rows, edge_cols, edge_vals.
// ---------------------------------------------------------------------------
extern "C" void kernel_launch(void* const* d_in, const int* in_sizes, int n_in,
                              void* d_out, int out_size) {
    const float4* x4   = (const float4*)d_in[0];
    const float*  W    = (const float*)d_in[1];
    const float*  b    = (const float*)d_in[2];
    const void*   rows = d_in[3];
    const void*   cols = d_in[4];
    const float*  vals = (const float*)d_in[5];
    float4* out = (float4*)d_out;

    int n_nodes = in_sizes[0] / IN_F;
    int n_edges = in_sizes[3];

    __half2* zh = nullptr;
    cudaGetSymbolAddress((void**)&zh, g_zh);

    // 1) z = x @ W + b via fp16 m16n8k16 MMA + cp.async pipeline (+ probe)
    int gemm_blocks = (n_nodes + NPB - 1) / NPB;   // 782
    gemm_kernel<<<gemm_blocks, GB>>>(
        x4, W, b, zh, n_nodes, (const long long*)rows);

    // 2) out[e] = w_e * (z[r] + z[c]), 4 consecutive edges/thread,
    //    8 lanes/edge, 256-thr blocks (one-shot grid).
    int M = (n_edges + 3) >> 2;
    long long total = (long long)M * 8;
    int edge_blocks = (int)((total + 255) / 256);
    edge_kernel<<<edge_blocks, 256>>>(zh, rows, cols, vals, out, n_edges);
}

// round 16
// speedup vs baseline: 1.0083x; 1.0083x over previous
#include <cuda_runtime.h>
#include <cuda_fp16.h>
#include <cstdint>

// ---------------------------------------------------------------------------
// EdgeDense: z = x @ W + b  (N x 32, stored fp16), then
//            out[e] = w_e * (z[rows[e]] + z[cols[e]])   (fp32 out)
// N_NODES = 100000, IN = 128, OUT = 32, E = 1.6M
// GEMM via fp16 mma.sync m16n8k16 (f32 accum) + 3-stage cp.async pipeline;
// edge kernel gather/scatter (config frozen since R11).
// R16 = R15 with the pipeline DRAIN FIX: the last chunk must wait_group 0
// (at c=7 chunk 7 is the newest committed group, so wait_group 1 could
// leave it in flight -- that was R15's rel_err 8.9e-3).
// ---------------------------------------------------------------------------

#define MAX_NODES 100000
#define IN_F 128
#define OUT_F 32

#define GB 256                  // gemm threads per block (8 warps)
#define NPB 128                 // nodes per block -> 782 blocks
#define NCH 8                   // k-chunks of 16
#define NST 3                   // pipeline stages (prefetch depth 2)
#define SXS 24                  // x staging stride (floats): 96B rows,
                                // conflict-free LDS.64 (8g+2t per phase)
#define ZTS 40                  // epilogue z tile stride (halves)

// z in fp16: 100000 * 32 * 2B = 6.4 MB (L2-resident). Device global.
__device__ __half2 g_zh[(size_t)MAX_NODES * (OUT_F / 2)];
// Index-dtype flag: 1 => indices are int64, 0 => indices are int32.
__device__ int g_idx64;

// Pack two fp32 into fp16x2 (lo first).
#define CVT_F16X2(d, hi, lo) \
    asm("cvt.rn.f16x2.f32 %0, %1, %2;" : "=r"(d) : "f"(hi), "f"(lo))

// 16B async copy global->shared; src_sz=0 => zero-fill (no src read).
#define CP_ASYNC16(dst_s, src_g, src_sz) \
    asm volatile("cp.async.ca.shared.global [%0], [%1], 16, %2;" \
                 :: "r"(dst_s), "l"(src_g), "r"(src_sz))
#define CP_COMMIT() asm volatile("cp.async.commit_group;")
#define CP_WAIT1()  asm volatile("cp.async.wait_group 1;" ::: "memory")
#define CP_WAIT0()  asm volatile("cp.async.wait_group 0;" ::: "memory")

// D(16x8,f32) += A(16x16,f16,row) * B(16x8,f16,col)
#define MMA_F16(d, a, b0, b1) \
    asm("mma.sync.aligned.m16n8k16.row.col.f32.f16.f16.f32 " \
        "{%0,%1,%2,%3}, {%4,%5,%6,%7}, {%8,%9}, {%0,%1,%2,%3};" \
        : "+f"((d)[0]), "+f"((d)[1]), "+f"((d)[2]), "+f"((d)[3]) \
        : "r"((a)[0]), "r"((a)[1]), "r"((a)[2]), "r"((a)[3]), \
          "r"(b0), "r"(b1))

// ---------------------------------------------------------------------------
// GEMM: z^T = W^T(32x128) @ x^T(128xN), m16n8k16 fp16 MMA, f32 accumulate.
// 3-stage cp.async pipeline (prefetch depth 2): prologue issues chunks 0,1;
// iteration c = wait (group c complete) -> syncthreads -> issue c+2 ->
// compute c. Wait rule: wait_group 1 for c < NCH-1 (newest pending group is
// chunk c+1), wait_group 0 for c == NCH-1 (chunk c IS the newest group).
// Buffer safety: chunk c+2 writes buf (c+2)%3 = (c-1)%3; every warp passed
// compute c-1 before the barrier in iteration c, so no overwrite race.
//   A = W^T fragments prebuilt PACKED fp16 in smem (8 KB; per-lane order,
//       1 LDS.128 per (mt, chunk)).
//   B = x staged fp32 (stride 24 floats, conflict-free LDS.64), pairs
//       cvt.rn.f16x2 at the operand load. fp16 inputs have the same 11-bit
//       mantissa as tf32 -> rel_err canary 3.5969e-4 must not move.
// m16n8k16 fragment maps (g=lane>>2, t=lane&3):
//   a0={A[g][2t],A[g][2t+1]}     a1={A[g+8][2t],A[g+8][2t+1]}
//   a2={A[g][2t+8],A[g][2t+9]}   a3={A[g+8][2t+8],A[g+8][2t+9]}
//   b0={B[2t][g],B[2t+1][g]}     b1={B[2t+8][g],B[2t+9][g]}
//   d0=D[g][2t] d1=D[g][2t+1] d2=D[g+8][2t] d3=D[g+8][2t+1]
// smem 44KB -> 5 CTAs/SM (wave count is not a binder per R12/13).
// Epilogue: bias, fp16, staged via smem (buffer 0 reused) for coalesced
// 16B stores. Block 0 runs the edge-index dtype probe (JAX x64-off hazard:
// int32 read as int64 words is >= 2^32 whenever the odd word != 0).
// ---------------------------------------------------------------------------
__global__ __launch_bounds__(GB)
void gemm_kernel(const float4* __restrict__ x4,
                 const float*  __restrict__ W,    // [128][32] row-major
                 const float*  __restrict__ b,    // [32]
                 __half2* __restrict__ zh,
                 int n_nodes,
                 const long long* __restrict__ idx_probe) {
    __shared__ unsigned sWf[2 * NCH * 32 * 4];    // 8 KB A fragments (fp16x2)
    __shared__ float sx[NST][NPB * SXS];          // 3 x 12 KB x buffers
    __shared__ int s_bad;

    int tid = threadIdx.x;
    int lane = tid & 31, wp = tid >> 5;           // wp 0..7
    int g = lane >> 2, t = lane & 3;
    int base = blockIdx.x * NPB;

    // Build packed-fp16 A fragments: sWf[((mt*NCH+kt)*32+lane)*4 + r]
    // A[o][k] = W[k*32+o].
    for (int idx = tid; idx < 2 * NCH * 32; idx += GB) {
        int mt = idx >> 8;                   // 0..1
        int kt = (idx >> 5) & 7;             // 0..7
        int ln = idx & 31;
        int gg = ln >> 2, tt = ln & 3;
        int k0 = kt * 16 + 2 * tt, ob = mt * 16 + gg;
        unsigned r0, r1, r2, r3;
        CVT_F16X2(r0, W[(k0 + 1) * OUT_F + ob],     W[k0 * OUT_F + ob]);
        CVT_F16X2(r1, W[(k0 + 1) * OUT_F + ob + 8], W[k0 * OUT_F + ob + 8]);
        CVT_F16X2(r2, W[(k0 + 9) * OUT_F + ob],     W[(k0 + 8) * OUT_F + ob]);
        CVT_F16X2(r3, W[(k0 + 9) * OUT_F + ob + 8], W[(k0 + 8) * OUT_F + ob + 8]);
        *reinterpret_cast<uint4*>(&sWf[idx * 4]) = make_uint4(r0, r1, r2, r3);
    }
    if (blockIdx.x == 0 && tid == 0) s_bad = 0;

    if (blockIdx.x == 0) {
        long long v = idx_probe[tid];
        if (v < 0 || v >= (long long)n_nodes) atomicOr(&s_bad, 1);
    }

    // Staging geometry: 2 x 16B cp.async per thread per chunk
    // (128 nodes x 64B per 16-k chunk = 512 float4).
    int sn[2], sq[2];
    unsigned ssz[2];
    const float4* gsrc[2];
    #pragma unroll
    for (int j = 0; j < 2; j++) {
        int i = j * GB + tid;
        sn[j] = i >> 2;                 // node 0..127
        sq[j] = i & 3;                  // float4 slot within 16-k chunk
        int gn = base + sn[j];
        ssz[j] = (gn < n_nodes) ? 16u : 0u;
        gsrc[j] = &x4[(size_t)(gn < n_nodes ? gn : 0) * (IN_F / 4) + sq[j]];
    }
    unsigned sdst[NST][2];
    #pragma unroll
    for (int bu = 0; bu < NST; bu++)
        #pragma unroll
        for (int j = 0; j < 2; j++)
            sdst[bu][j] = (unsigned)__cvta_generic_to_shared(
                &sx[bu][sn[j] * SXS + sq[j] * 4]);

    // Prologue: issue chunks 0 and 1 (two groups in flight).
    #pragma unroll
    for (int j = 0; j < 2; j++) CP_ASYNC16(sdst[0][j], gsrc[j], ssz[j]);
    CP_COMMIT();
    #pragma unroll
    for (int j = 0; j < 2; j++) CP_ASYNC16(sdst[1][j], gsrc[j] + 4, ssz[j]);
    CP_COMMIT();

    float d[2][2][4];
    #pragma unroll
    for (int mt = 0; mt < 2; mt++)
        #pragma unroll
        for (int nt = 0; nt < 2; nt++)
            #pragma unroll
            for (int r = 0; r < 4; r++) d[mt][nt][r] = 0.f;

    #pragma unroll
    for (int c = 0; c < NCH; c++) {
        // Drain rule: for c < NCH-1 the newest committed group is chunk
        // c+1, so <=1 pending guarantees chunk c. At c == NCH-1 chunk c is
        // itself the newest group -> must wait for ALL groups.
        if (c == NCH - 1) { CP_WAIT0(); } else { CP_WAIT1(); }
        __syncthreads();   // chunk c visible; all warps past compute c-1

        if (c + 2 < NCH) {
            #pragma unroll
            for (int j = 0; j < 2; j++)
                CP_ASYNC16(sdst[(c + 2) % NST][j],
                           gsrc[j] + (c + 2) * 4, ssz[j]);
            CP_COMMIT();
        }

        const float* xb = sx[c % NST];

        // A fragments for this chunk (one LDS.128 per mt, conflict-free).
        unsigned a[2][4];
        #pragma unroll
        for (int mt = 0; mt < 2; mt++)
            *reinterpret_cast<uint4*>(a[mt]) =
                *reinterpret_cast<const uint4*>(
                    &sWf[((mt * NCH + c) * 32 + lane) * 4]);

        #pragma unroll
        for (int nt = 0; nt < 2; nt++) {
            int nl = wp * 16 + nt * 8 + g;
            float2 v0 = *reinterpret_cast<const float2*>(
                &xb[nl * SXS + 2 * t]);
            float2 v1 = *reinterpret_cast<const float2*>(
                &xb[nl * SXS + 8 + 2 * t]);
            unsigned b0, b1;
            CVT_F16X2(b0, v0.y, v0.x);
            CVT_F16X2(b1, v1.y, v1.x);
            MMA_F16(d[0][nt], a[0], b0, b1);
            MMA_F16(d[1][nt], a[1], b0, b1);
        }
    }
    __syncthreads();   // all MMAs done before buffer 0 is reused as zt

    // Epilogue: bias + fp16, stage via smem (sx[0] reused, half zt[128][40]).
    float bias_v[4];
    bias_v[0] = __ldg(&b[g]);
    bias_v[1] = __ldg(&b[g + 8]);
    bias_v[2] = __ldg(&b[16 + g]);
    bias_v[3] = __ldg(&b[16 + g + 8]);

    __half* zt = reinterpret_cast<__half*>(sx[0]);
    #pragma unroll
    for (int mt = 0; mt < 2; mt++) {
        #pragma unroll
        for (int nt = 0; nt < 2; nt++) {
            int n0 = wp * 16 + nt * 8 + 2 * t;
            int o0 = mt * 16 + g;
            zt[n0 * ZTS + o0]           = __float2half(d[mt][nt][0] + bias_v[mt * 2]);
            zt[(n0 + 1) * ZTS + o0]     = __float2half(d[mt][nt][1] + bias_v[mt * 2]);
            zt[n0 * ZTS + o0 + 8]       = __float2half(d[mt][nt][2] + bias_v[mt * 2 + 1]);
            zt[(n0 + 1) * ZTS + o0 + 8] = __float2half(d[mt][nt][3] + bias_v[mt * 2 + 1]);
        }
    }
    __syncthreads();

    // Coalesced store: 128 nodes x 64B, 2 x 16B per thread.
    #pragma unroll
    for (int p = 0; p < 2; p++) {
        int i = p * GB + tid;           // 0..511
        int nl = i >> 2;
        int part = i & 3;
        int node = base + nl;
        if (node < n_nodes) {
            uint4 v = *reinterpret_cast<const uint4*>(&zt[nl * ZTS + part * 8]);
            *reinterpret_cast<uint4*>(
                reinterpret_cast<char*>(zh) + (size_t)node * 64 + part * 16) = v;
        }
    }

    if (blockIdx.x == 0) {
        __syncthreads();
        if (tid == 0) g_idx64 = s_bad ? 0 : 1;
    }
}

// ---------------------------------------------------------------------------
// Edge kernel: byte-identical to R11-R14 (measured 47.7-48.3us -- family
// optimum; all lane-width / occupancy / persistence perturbations
// regressed). 8 lanes per edge, uint2 __ldcg gathers (4 distinct z rows
// per gather instr; L1 fill skipped); 4 CONSECUTIVE edges per thread with
// vectorized index/val loads; front-batched gathers (MLP=8); stores
// 1 STG.128/lane/edge, streaming.
// ---------------------------------------------------------------------------
__global__ __launch_bounds__(256)
void edge_kernel(const __half2* __restrict__ zh,
                 const void* __restrict__ rows_raw,
                 const void* __restrict__ cols_raw,
                 const float* __restrict__ vals,
                 float4* __restrict__ out,
                 int n_edges) {
    int gid = blockIdx.x * blockDim.x + threadIdx.x;
    int m = gid >> 3;
    int c = gid & 7;
    int eb = m * 4;
    if (eb >= n_edges) return;

    const uint2* zb = reinterpret_cast<const uint2*>(zh);

    if (eb + 3 < n_edges) {
        int r[4], cc[4];
        float w[4];
        if (g_idx64) {
            const int4* rp = (const int4*)rows_raw;
            const int4* cp = (const int4*)cols_raw;
            int4 ra = __ldcs(&rp[2 * m]), rb = __ldcs(&rp[2 * m + 1]);
            int4 ca = __ldcs(&cp[2 * m]), cb = __ldcs(&cp[2 * m + 1]);
            r[0] = ra.x; r[1] = ra.z; r[2] = rb.x; r[3] = rb.z;
            cc[0] = ca.x; cc[1] = ca.z; cc[2] = cb.x; cc[3] = cb.z;
        } else {
            int4 ra = __ldcs(&((const int4*)rows_raw)[m]);
            int4 ca = __ldcs(&((const int4*)cols_raw)[m]);
            r[0] = ra.x; r[1] = ra.y; r[2] = ra.z; r[3] = ra.w;
            cc[0] = ca.x; cc[1] = ca.y; cc[2] = ca.z; cc[3] = ca.w;
        }
        float4 wv = __ldcs(&((const float4*)vals)[m]);
        w[0] = wv.x; w[1] = wv.y; w[2] = wv.z; w[3] = wv.w;

        uint2 ga[4], gd[4];
        #pragma unroll
        for (int q = 0; q < 4; q++) {
            ga[q] = __ldcg(&zb[(size_t)r[q] * 8 + c]);
            gd[q] = __ldcg(&zb[(size_t)cc[q] * 8 + c]);
        }

        #pragma unroll
        for (int q = 0; q < 4; q++) {
            float2 fa0 = __half22float2(*reinterpret_cast<__half2*>(&ga[q].x));
            float2 fd0 = __half22float2(*reinterpret_cast<__half2*>(&gd[q].x));
            float2 fa1 = __half22float2(*reinterpret_cast<__half2*>(&ga[q].y));
            float2 fd1 = __half22float2(*reinterpret_cast<__half2*>(&gd[q].y));
            float4 o;
            o.x = w[q] * (fa0.x + fd0.x);
            o.y = w[q] * (fa0.y + fd0.y);
            o.z = w[q] * (fa1.x + fd1.x);
            o.w = w[q] * (fa1.y + fd1.y);
            __stcs(&out[(size_t)(eb + q) * 8 + c], o);
        }
    } else {
        // Tail: per-edge guarded scalar path.
        int sh = g_idx64;
        const int* rp = (const int*)rows_raw;
        const int* cp = (const int*)cols_raw;
        for (int q = 0; q < 4; q++) {
            int e = eb + q;
            if (e >= n_edges) break;
            int rr = __ldcs(&rp[e << sh]);
            int cl = __ldcs(&cp[e << sh]);
            float ww = __ldcs(&vals[e]);
            uint2 a = __ldcg(&zb[(size_t)rr * 8 + c]);
            uint2 dd = __ldcg(&zb[(size_t)cl * 8 + c]);
            float2 fa0 = __half22float2(*reinterpret_cast<__half2*>(&a.x));
            float2 fd0 = __half22float2(*reinterpret_cast<__half2*>(&dd.x));
            float2 fa1 = __half22float2(*reinterpret_cast<__half2*>(&a.y));
            float2 fd1 = __half22float2(*reinterpret_cast<__half2*>(&dd.y));
            float4 o;
            o.x = ww * (fa0.x + fd0.x);
            o.y = ww * (fa0.y + fd0.y);
            o.z = ww * (fa1.x + fd1.x);
            o.w = ww * (fa1.y + fd1.y);
            __stcs(&out[(size_t)e * 8 + c], o);
        }
    }
}

// ---------------------------------------------------------------------------
// Launch. Inputs (metadata order): x, W, b, edge_rows, edge_cols, edge_vals.
// ---------------------------------------------------------------------------
extern "C" void kernel_launch(void* const* d_in, const int* in_sizes, int n_in,
                              void* d_out, int out_size) {
    const float4* x4   = (const float4*)d_in[0];
    const float*  W    = (const float*)d_in[1];
    const float*  b    = (const float*)d_in[2];
    const void*   rows = d_in[3];
    const void*   cols = d_in[4];
    const float*  vals = (const float*)d_in[5];
    float4* out = (float4*)d_out;

    int n_nodes = in_sizes[0] / IN_F;
    int n_edges = in_sizes[3];

    __half2* zh = nullptr;
    cudaGetSymbolAddress((void**)&zh, g_zh);

    // 1) z = x @ W + b via fp16 m16n8k16 MMA + 3-stage cp.async pipeline
    int gemm_blocks = (n_nodes + NPB - 1) / NPB;   // 782
    gemm_kernel<<<gemm_blocks, GB>>>(
        x4, W, b, zh, n_nodes, (const long long*)rows);

    // 2) out[e] = w_e * (z[r] + z[c]), 4 consecutive edges/thread,
    //    8 lanes/edge, 256-thr blocks (one-shot grid).
    int M = (n_edges + 3) >> 2;
    long long total = (long long)M * 8;
    int edge_blocks = (int)((total + 255) / 256);
    edge_kernel<<<edge_blocks, 256>>>(zh, rows, cols, vals, out, n_edges);
}

// round 17
// speedup vs baseline: 1.0667x; 1.0579x over previous
#include <cuda_runtime.h>
#include <cuda_fp16.h>
#include <cstdint>

// ---------------------------------------------------------------------------
// EdgeDense: z = x @ W + b  (N x 32, stored fp16), then
//            out[e] = w_e * (z[rows[e]] + z[cols[e]])   (fp32 out)
// N_NODES = 100000, IN = 128, OUT = 32, E = 1.6M
// GEMM via fp16 mma.sync m16n8k16 + 3-stage cp.async pipeline.
// Edge kernel launched with PDL (programmatic stream serialization): its
// z-independent prologue (dtype probe + index/val loads) overlaps the
// gemm's drain; cudaGridDependencySynchronize() guards the z gathers.
// ---------------------------------------------------------------------------

#define MAX_NODES 100000
#define IN_F 128
#define OUT_F 32

#define GB 256                  // gemm threads per block (8 warps)
#define NPB 128                 // nodes per block -> 782 blocks
#define NCH 8                   // k-chunks of 16
#define NST 3                   // pipeline stages (prefetch depth 2)
#define SXS 24                  // x staging stride (floats)
#define ZTS 40                  // epilogue z tile stride (halves)

// z in fp16: 100000 * 32 * 2B = 6.4 MB (L2-resident). Device global.
__device__ __half2 g_zh[(size_t)MAX_NODES * (OUT_F / 2)];

// Pack two fp32 into fp16x2 (lo first).
#define CVT_F16X2(d, hi, lo) \
    asm("cvt.rn.f16x2.f32 %0, %1, %2;" : "=r"(d) : "f"(hi), "f"(lo))

// 16B async copy global->shared; src_sz=0 => zero-fill (no src read).
#define CP_ASYNC16(dst_s, src_g, src_sz) \
    asm volatile("cp.async.ca.shared.global [%0], [%1], 16, %2;" \
                 :: "r"(dst_s), "l"(src_g), "r"(src_sz))
#define CP_COMMIT() asm volatile("cp.async.commit_group;")
#define CP_WAIT1()  asm volatile("cp.async.wait_group 1;" ::: "memory")
#define CP_WAIT0()  asm volatile("cp.async.wait_group 0;" ::: "memory")

// D(16x8,f32) += A(16x16,f16,row) * B(16x8,f16,col)
#define MMA_F16(d, a, b0, b1) \
    asm("mma.sync.aligned.m16n8k16.row.col.f32.f16.f16.f32 " \
        "{%0,%1,%2,%3}, {%4,%5,%6,%7}, {%8,%9}, {%0,%1,%2,%3};" \
        : "+f"((d)[0]), "+f"((d)[1]), "+f"((d)[2]), "+f"((d)[3]) \
        : "r"((a)[0]), "r"((a)[1]), "r"((a)[2]), "r"((a)[3]), \
          "r"(b0), "r"(b1))

// ---------------------------------------------------------------------------
// GEMM (R16 version, measured ~17us wall incl. launch; rel_err canary
// 3.5969e-4): z^T = W^T(32x128) @ x^T(128xN), m16n8k16 fp16 MMA, f32 accum.
// 3-stage cp.async pipeline; drain rule: wait_group 1 for c < NCH-1,
// wait_group 0 for the final chunk (it is itself the newest group).
// The edge-index dtype probe has MOVED to the edge kernel (self-contained),
// removing the cross-kernel g_idx64 dependency so PDL can overlap.
// Fragment maps (g=lane>>2, t=lane&3):
//   a0={A[g][2t],A[g][2t+1]}     a1={A[g+8][2t],A[g+8][2t+1]}
//   a2={A[g][2t+8],A[g][2t+9]}   a3={A[g+8][2t+8],A[g+8][2t+9]}
//   b0={B[2t][g],B[2t+1][g]}     b1={B[2t+8][g],B[2t+9][g]}
//   d0=D[g][2t] d1=D[g][2t+1] d2=D[g+8][2t] d3=D[g+8][2t+1]
// ---------------------------------------------------------------------------
__global__ __launch_bounds__(GB)
void gemm_kernel(const float4* __restrict__ x4,
                 const float*  __restrict__ W,    // [128][32] row-major
                 const float*  __restrict__ b,    // [32]
                 __half2* __restrict__ zh,
                 int n_nodes) {
    __shared__ unsigned sWf[2 * NCH * 32 * 4];    // 8 KB A fragments (fp16x2)
    __shared__ float sx[NST][NPB * SXS];          // 3 x 12 KB x buffers

    int tid = threadIdx.x;
    int lane = tid & 31, wp = tid >> 5;           // wp 0..7
    int g = lane >> 2, t = lane & 3;
    int base = blockIdx.x * NPB;

    // Build packed-fp16 A fragments: sWf[((mt*NCH+kt)*32+lane)*4 + r]
    for (int idx = tid; idx < 2 * NCH * 32; idx += GB) {
        int mt = idx >> 8;
        int kt = (idx >> 5) & 7;
        int ln = idx & 31;
        int gg = ln >> 2, tt = ln & 3;
        int k0 = kt * 16 + 2 * tt, ob = mt * 16 + gg;
        unsigned r0, r1, r2, r3;
        CVT_F16X2(r0, W[(k0 + 1) * OUT_F + ob],     W[k0 * OUT_F + ob]);
        CVT_F16X2(r1, W[(k0 + 1) * OUT_F + ob + 8], W[k0 * OUT_F + ob + 8]);
        CVT_F16X2(r2, W[(k0 + 9) * OUT_F + ob],     W[(k0 + 8) * OUT_F + ob]);
        CVT_F16X2(r3, W[(k0 + 9) * OUT_F + ob + 8], W[(k0 + 8) * OUT_F + ob + 8]);
        *reinterpret_cast<uint4*>(&sWf[idx * 4]) = make_uint4(r0, r1, r2, r3);
    }

    // Staging geometry: 2 x 16B cp.async per thread per chunk.
    int sn[2], sq[2];
    unsigned ssz[2];
    const float4* gsrc[2];
    #pragma unroll
    for (int j = 0; j < 2; j++) {
        int i = j * GB + tid;
        sn[j] = i >> 2;
        sq[j] = i & 3;
        int gn = base + sn[j];
        ssz[j] = (gn < n_nodes) ? 16u : 0u;
        gsrc[j] = &x4[(size_t)(gn < n_nodes ? gn : 0) * (IN_F / 4) + sq[j]];
    }
    unsigned sdst[NST][2];
    #pragma unroll
    for (int bu = 0; bu < NST; bu++)
        #pragma unroll
        for (int j = 0; j < 2; j++)
            sdst[bu][j] = (unsigned)__cvta_generic_to_shared(
                &sx[bu][sn[j] * SXS + sq[j] * 4]);

    // Prologue: issue chunks 0 and 1.
    #pragma unroll
    for (int j = 0; j < 2; j++) CP_ASYNC16(sdst[0][j], gsrc[j], ssz[j]);
    CP_COMMIT();
    #pragma unroll
    for (int j = 0; j < 2; j++) CP_ASYNC16(sdst[1][j], gsrc[j] + 4, ssz[j]);
    CP_COMMIT();

    float d[2][2][4];
    #pragma unroll
    for (int mt = 0; mt < 2; mt++)
        #pragma unroll
        for (int nt = 0; nt < 2; nt++)
            #pragma unroll
            for (int r = 0; r < 4; r++) d[mt][nt][r] = 0.f;

    #pragma unroll
    for (int c = 0; c < NCH; c++) {
        if (c == NCH - 1) { CP_WAIT0(); } else { CP_WAIT1(); }
        __syncthreads();

        if (c + 2 < NCH) {
            #pragma unroll
            for (int j = 0; j < 2; j++)
                CP_ASYNC16(sdst[(c + 2) % NST][j],
                           gsrc[j] + (c + 2) * 4, ssz[j]);
            CP_COMMIT();
        }

        const float* xb = sx[c % NST];

        unsigned a[2][4];
        #pragma unroll
        for (int mt = 0; mt < 2; mt++)
            *reinterpret_cast<uint4*>(a[mt]) =
                *reinterpret_cast<const uint4*>(
                    &sWf[((mt * NCH + c) * 32 + lane) * 4]);

        #pragma unroll
        for (int nt = 0; nt < 2; nt++) {
            int nl = wp * 16 + nt * 8 + g;
            float2 v0 = *reinterpret_cast<const float2*>(
                &xb[nl * SXS + 2 * t]);
            float2 v1 = *reinterpret_cast<const float2*>(
                &xb[nl * SXS + 8 + 2 * t]);
            unsigned b0, b1;
            CVT_F16X2(b0, v0.y, v0.x);
            CVT_F16X2(b1, v1.y, v1.x);
            MMA_F16(d[0][nt], a[0], b0, b1);
            MMA_F16(d[1][nt], a[1], b0, b1);
        }
    }
    __syncthreads();

    // Epilogue: bias + fp16, stage via smem (sx[0] reused, half zt[128][40]).
    float bias_v[4];
    bias_v[0] = __ldg(&b[g]);
    bias_v[1] = __ldg(&b[g + 8]);
    bias_v[2] = __ldg(&b[16 + g]);
    bias_v[3] = __ldg(&b[16 + g + 8]);

    __half* zt = reinterpret_cast<__half*>(sx[0]);
    #pragma unroll
    for (int mt = 0; mt < 2; mt++) {
        #pragma unroll
        for (int nt = 0; nt < 2; nt++) {
            int n0 = wp * 16 + nt * 8 + 2 * t;
            int o0 = mt * 16 + g;
            zt[n0 * ZTS + o0]           = __float2half(d[mt][nt][0] + bias_v[mt * 2]);
            zt[(n0 + 1) * ZTS + o0]     = __float2half(d[mt][nt][1] + bias_v[mt * 2]);
            zt[n0 * ZTS + o0 + 8]       = __float2half(d[mt][nt][2] + bias_v[mt * 2 + 1]);
            zt[(n0 + 1) * ZTS + o0 + 8] = __float2half(d[mt][nt][3] + bias_v[mt * 2 + 1]);
        }
    }
    __syncthreads();

    // Coalesced store: 128 nodes x 64B, 2 x 16B per thread.
    #pragma unroll
    for (int p = 0; p < 2; p++) {
        int i = p * GB + tid;
        int nl = i >> 2;
        int part = i & 3;
        int node = base + nl;
        if (node < n_nodes) {
            uint4 v = *reinterpret_cast<const uint4*>(&zt[nl * ZTS + part * 8]);
            *reinterpret_cast<uint4*>(
                reinterpret_cast<char*>(zh) + (size_t)node * 64 + part * 16) = v;
        }
    }
}

// ---------------------------------------------------------------------------
// Edge kernel (PDL secondary). Gather/compute config byte-identical to
// R11-R16 (measured 47.7-48.5us, family optimum). New structure for PDL:
//   1. SELF-CONTAINED index-dtype probe: __syncthreads_or over the first
//      256 int64 words of rows (pure input -> legal before the dependency
//      sync). int32 data read as int64 is >= 2^32 whenever the odd word
//      != 0 -- unambiguous over 256 words of uniform indices < 100000.
//   2. Load this thread's indices/vals (z-independent).
//   3. cudaGridDependencySynchronize() -- wait for gemm's z.
//   4. Gather z (__ldcg), compute, streaming stores.
// Steps 1-2 overlap the gemm's drain under programmatic stream
// serialization.
// ---------------------------------------------------------------------------
__global__ __launch_bounds__(256)
void edge_kernel(const __half2* __restrict__ zh,
                 const void* __restrict__ rows_raw,
                 const void* __restrict__ cols_raw,
                 const float* __restrict__ vals,
                 float4* __restrict__ out,
                 int n_edges, int n_nodes) {
    int tid = threadIdx.x;

    // --- 1. dtype probe (block-local, input-only) ---
    int bad = 0;
    int nw = n_edges >> 1;                  // int64 words available if int32
    if (nw > 256) nw = 256;
    if (tid < nw) {
        long long v = ((const long long*)rows_raw)[tid];
        if (v < 0 || v >= (long long)n_nodes) bad = 1;
    }
    int sh = __syncthreads_or(bad) ? 0 : 1; // bad => int32 layout

    int gid = blockIdx.x * blockDim.x + tid;
    int m = gid >> 3;
    int c = gid & 7;
    int eb = m * 4;
    if (eb >= n_edges) {
        cudaGridDependencySynchronize();    // still participate in PDL sync
        return;
    }

    const uint2* zb = reinterpret_cast<const uint2*>(zh);

    if (eb + 3 < n_edges) {
        // --- 2. z-independent index/val loads (overlap gemm drain) ---
        int r[4], cc[4];
        float w[4];
        if (sh) {
            const int4* rp = (const int4*)rows_raw;
            const int4* cp = (const int4*)cols_raw;
            int4 ra = __ldcs(&rp[2 * m]), rb = __ldcs(&rp[2 * m + 1]);
            int4 ca = __ldcs(&cp[2 * m]), cb = __ldcs(&cp[2 * m + 1]);
            r[0] = ra.x; r[1] = ra.z; r[2] = rb.x; r[3] = rb.z;
            cc[0] = ca.x; cc[1] = ca.z; cc[2] = cb.x; cc[3] = cb.z;
        } else {
            int4 ra = __ldcs(&((const int4*)rows_raw)[m]);
            int4 ca = __ldcs(&((const int4*)cols_raw)[m]);
            r[0] = ra.x; r[1] = ra.y; r[2] = ra.z; r[3] = ra.w;
            cc[0] = ca.x; cc[1] = ca.y; cc[2] = ca.z; cc[3] = ca.w;
        }
        float4 wv = __ldcs(&((const float4*)vals)[m]);
        w[0] = wv.x; w[1] = wv.y; w[2] = wv.z; w[3] = wv.w;

        // --- 3. wait for gemm's z stores to be visible ---
        cudaGridDependencySynchronize();

        // --- 4. gathers + compute + streaming stores ---
        uint2 ga[4], gd[4];
        #pragma unroll
        for (int q = 0; q < 4; q++) {
            ga[q] = __ldcg(&zb[(size_t)r[q] * 8 + c]);
            gd[q] = __ldcg(&zb[(size_t)cc[q] * 8 + c]);
        }

        #pragma unroll
        for (int q = 0; q < 4; q++) {
            float2 fa0 = __half22float2(*reinterpret_cast<__half2*>(&ga[q].x));
            float2 fd0 = __half22float2(*reinterpret_cast<__half2*>(&gd[q].x));
            float2 fa1 = __half22float2(*reinterpret_cast<__half2*>(&ga[q].y));
            float2 fd1 = __half22float2(*reinterpret_cast<__half2*>(&gd[q].y));
            float4 o;
            o.x = w[q] * (fa0.x + fd0.x);
            o.y = w[q] * (fa0.y + fd0.y);
            o.z = w[q] * (fa1.x + fd1.x);
            o.w = w[q] * (fa1.y + fd1.y);
            __stcs(&out[(size_t)(eb + q) * 8 + c], o);
        }
    } else {
        // Tail: per-edge guarded scalar path.
        const int* rp = (const int*)rows_raw;
        const int* cp = (const int*)cols_raw;
        int rr[4], cl[4];
        float ww[4];
        int cnt = 0;
        for (int q = 0; q < 4; q++) {
            int e = eb + q;
            if (e >= n_edges) break;
            rr[q] = __ldcs(&rp[e << sh]);
            cl[q] = __ldcs(&cp[e << sh]);
            ww[q] = __ldcs(&vals[e]);
            cnt++;
        }
        cudaGridDependencySynchronize();
        for (int q = 0; q < cnt; q++) {
            int e = eb + q;
            uint2 a = __ldcg(&zb[(size_t)rr[q] * 8 + c]);
            uint2 dd = __ldcg(&zb[(size_t)cl[q] * 8 + c]);
            float2 fa0 = __half22float2(*reinterpret_cast<__half2*>(&a.x));
            float2 fd0 = __half22float2(*reinterpret_cast<__half2*>(&dd.x));
            float2 fa1 = __half22float2(*reinterpret_cast<__half2*>(&a.y));
            float2 fd1 = __half22float2(*reinterpret_cast<__half2*>(&dd.y));
            float4 o;
            o.x = ww[q] * (fa0.x + fd0.x);
            o.y = ww[q] * (fa0.y + fd0.y);
            o.z = ww[q] * (fa1.x + fd1.x);
            o.w = ww[q] * (fa1.y + fd1.y);
            __stcs(&out[(size_t)e * 8 + c], o);
        }
    }
}

// ---------------------------------------------------------------------------
// Launch. Inputs (metadata order): x, W, b, edge_rows, edge_cols, edge_vals.
// Edge kernel launched with programmatic stream serialization so its
// z-independent prologue overlaps the gemm's drain.
// ---------------------------------------------------------------------------
extern "C" void kernel_launch(void* const* d_in, const int* in_sizes, int n_in,
                              void* d_out, int out_size) {
    const float4* x4   = (const float4*)d_in[0];
    const float*  W    = (const float*)d_in[1];
    const float*  b    = (const float*)d_in[2];
    const void*   rows = d_in[3];
    const void*   cols = d_in[4];
    const float*  vals = (const float*)d_in[5];
    float4* out = (float4*)d_out;

    int n_nodes = in_sizes[0] / IN_F;
    int n_edges = in_sizes[3];

    __half2* zh = nullptr;
    cudaGetSymbolAddress((void**)&zh, g_zh);

    // 1) z = x @ W + b via fp16 m16n8k16 MMA + 3-stage cp.async pipeline
    int gemm_blocks = (n_nodes + NPB - 1) / NPB;   // 782
    gemm_kernel<<<gemm_blocks, GB>>>(x4, W, b, zh, n_nodes);

    // 2) edge kernel with PDL overlap
    int M = (n_edges + 3) >> 2;
    long long total = (long long)M * 8;
    int edge_blocks = (int)((total + 255) / 256);

    cudaLaunchConfig_t cfg = {};
    cfg.gridDim = dim3(edge_blocks, 1, 1);
    cfg.blockDim = dim3(256, 1, 1);
    cfg.dynamicSmemBytes = 0;
    cudaLaunchAttribute attrs[1];
    attrs[0].id = cudaLaunchAttributeProgrammaticStreamSerialization;
    attrs[0].val.programmaticStreamSerializationAllowed = 1;
    cfg.attrs = attrs;
    cfg.numAttrs = 1;
    cudaLaunchKernelEx(&cfg, edge_kernel,
                       (const __half2*)zh, rows, cols, vals, out,
                       n_edges, n_nodes);
}